// round 2
// baseline (speedup 1.0000x reference)
#include <cuda_runtime.h>
#include <cuda_bf16.h>
#include <math.h>

// ---------------- Problem constants ----------------
// x: [8, 4096, 512] f32; W_qkv: [1536, 512]; W_proj: [512, 512]; b_proj: [512]
// H = W = 64, Hh = Wh = 32, nW = 1024, T = 4, nh = 8, hd = 64, scale = 1/8
#define Bc 8
#define Ntok 4096
#define Cch 512
#define NHI 1024   // pooled tokens
#define NH 8
#define HD 64

// ---------------- Scratch (device globals; no allocation allowed) ----------------
__device__ float g_xhi[Bc * NHI * Cch];              // 16 MB
__device__ float g_qkv_hi[(size_t)Bc * NHI * 1536];  // 50 MB
__device__ float g_S[64ull * 1024 * 1024];           // 268 MB  (B*nh batched logits)
__device__ float g_out_hi[Bc * NHI * Cch];           // 16 MB
__device__ float g_win[(size_t)Bc * 1024 * 4 * 512]; // 67 MB   (gathered windows A-matrix)
__device__ float g_Wlo[1536 * 512];                  // 3 MB    (K-permuted W_qkv)
__device__ float g_qkv_lo[(size_t)Bc * 1024 * 4 * 1536]; // 201 MB
__device__ float g_sum[(size_t)Bc * Ntok * Cch];     // 67 MB   (hi_up + lo)

// ---------------- Generic batched SGEMM: C[m,n] = alpha * sum_k A[m,k]*B'[n,k] (+bias) ----
// TRANSB=false: B'[n,k] = B[n*ldb + k]   (both operands K-contiguous)
// TRANSB=true : B'[n,k] = B[k*ldb + n]
// Batch z decomposed as zb=z/hdiv, zh=z%hdiv; base offsets zb*s?b + zh*s?h.
#define BM 128
#define BN 128
#define BKK 16

template <bool TRANSB, bool HASBIAS>
__global__ __launch_bounds__(256) void sgemm_kernel(
    const float* __restrict__ A, int lda, long long sAb, long long sAh,
    const float* __restrict__ B, int ldb, long long sBb, long long sBh,
    float* __restrict__ C, int ldc, long long sCb, long long sCh,
    const float* __restrict__ bias,
    int M, int N, int K, float alpha, int hdiv)
{
    __shared__ __align__(16) float As[BKK][BM + 4];
    __shared__ __align__(16) float Bs[BKK][BN + 4];

    int z = blockIdx.z;
    int zb = z / hdiv, zh = z % hdiv;
    A += zb * sAb + zh * sAh;
    B += zb * sBb + zh * sBh;
    C += zb * sCb + zh * sCh;

    int bm = blockIdx.y * BM;
    int bn = blockIdx.x * BN;
    int tid = threadIdx.x;
    int tx = tid & 15, ty = tid >> 4;

    float acc[8][8];
#pragma unroll
    for (int i = 0; i < 8; i++)
#pragma unroll
        for (int j = 0; j < 8; j++) acc[i][j] = 0.f;

    for (int k0 = 0; k0 < K; k0 += BKK) {
        // load A tile [BM x BKK] -> transposed As[k][m]
#pragma unroll
        for (int r = 0; r < 2; r++) {
            int f = tid + r * 256;
            int row = f >> 2, kq = (f & 3) * 4;
            float4 v = *(const float4*)&A[(long long)(bm + row) * lda + k0 + kq];
            As[kq + 0][row] = v.x; As[kq + 1][row] = v.y;
            As[kq + 2][row] = v.z; As[kq + 3][row] = v.w;
        }
        if (!TRANSB) {
#pragma unroll
            for (int r = 0; r < 2; r++) {
                int f = tid + r * 256;
                int row = f >> 2, kq = (f & 3) * 4;
                int n = bn + row;
                float4 v = make_float4(0.f, 0.f, 0.f, 0.f);
                if (n < N) v = *(const float4*)&B[(long long)n * ldb + k0 + kq];
                Bs[kq + 0][row] = v.x; Bs[kq + 1][row] = v.y;
                Bs[kq + 2][row] = v.z; Bs[kq + 3][row] = v.w;
            }
        } else {
#pragma unroll
            for (int r = 0; r < 2; r++) {
                int f = tid + r * 256;
                int kr = f >> 5, n4 = (f & 31) * 4;
                int n = bn + n4;
                float4 v = make_float4(0.f, 0.f, 0.f, 0.f);
                if (n < N) v = *(const float4*)&B[(long long)(k0 + kr) * ldb + n];
                *(float4*)&Bs[kr][n4] = v;
            }
        }
        __syncthreads();
#pragma unroll
        for (int kk = 0; kk < BKK; kk++) {
            float a[8], b[8];
            *(float4*)&a[0] = *(const float4*)&As[kk][ty * 8];
            *(float4*)&a[4] = *(const float4*)&As[kk][ty * 8 + 4];
            *(float4*)&b[0] = *(const float4*)&Bs[kk][tx * 8];
            *(float4*)&b[4] = *(const float4*)&Bs[kk][tx * 8 + 4];
#pragma unroll
            for (int i = 0; i < 8; i++)
#pragma unroll
                for (int j = 0; j < 8; j++) acc[i][j] += a[i] * b[j];
        }
        __syncthreads();
    }

#pragma unroll
    for (int i = 0; i < 8; i++) {
        int m = bm + ty * 8 + i;
#pragma unroll
        for (int j = 0; j < 8; j += 4) {
            int n = bn + tx * 8 + j;
            if (n < N) {
                float4 v;
                v.x = acc[i][j + 0] * alpha;
                v.y = acc[i][j + 1] * alpha;
                v.z = acc[i][j + 2] * alpha;
                v.w = acc[i][j + 3] * alpha;
                if (HASBIAS) {
                    v.x += bias[n + 0]; v.y += bias[n + 1];
                    v.z += bias[n + 2]; v.w += bias[n + 3];
                }
                *(float4*)&C[(long long)m * ldc + n] = v;
            }
        }
    }
}

// ---------------- 2x2 average pool: x [B,64,64,C] -> g_xhi [B,32,32,C] ----------------
__global__ void pool_kernel(const float* __restrict__ x)
{
    int gid = blockIdx.x * 256 + threadIdx.x;  // B*1024*128 float4s
    int c4 = gid & 127;
    int hw = (gid >> 7) & 1023;
    int b = gid >> 17;
    int wh = hw >> 5, ww = hw & 31;
    int n0 = (wh * 2) * 64 + ww * 2;
    const float4* xb = (const float4*)(x + (size_t)b * Ntok * Cch);
    float4 a = xb[(size_t)n0 * 128 + c4];
    float4 bv = xb[(size_t)(n0 + 1) * 128 + c4];
    float4 c = xb[(size_t)(n0 + 64) * 128 + c4];
    float4 d = xb[(size_t)(n0 + 65) * 128 + c4];
    float4 o;
    o.x = (a.x + bv.x + c.x + d.x) * 0.25f;
    o.y = (a.y + bv.y + c.y + d.y) * 0.25f;
    o.z = (a.z + bv.z + c.z + d.z) * 0.25f;
    o.w = (a.w + bv.w + c.w + d.w) * 0.25f;
    ((float4*)g_xhi)[gid] = o;
}

// ---------------- Row softmax over 1024 columns (in place) ----------------
__global__ void softmax_kernel(float* __restrict__ S)
{
    float* row = S + (size_t)blockIdx.x * 1024;
    int tid = threadIdx.x;  // 256
    __shared__ float redm[8], reds[8];
    float v[4];
    float mx = -1e30f;
#pragma unroll
    for (int i = 0; i < 4; i++) { v[i] = row[tid + i * 256]; mx = fmaxf(mx, v[i]); }
#pragma unroll
    for (int o = 16; o > 0; o >>= 1) mx = fmaxf(mx, __shfl_xor_sync(0xffffffffu, mx, o));
    if ((tid & 31) == 0) redm[tid >> 5] = mx;
    __syncthreads();
    mx = redm[0];
#pragma unroll
    for (int i = 1; i < 8; i++) mx = fmaxf(mx, redm[i]);
    float s = 0.f;
#pragma unroll
    for (int i = 0; i < 4; i++) { v[i] = __expf(v[i] - mx); s += v[i]; }
#pragma unroll
    for (int o = 16; o > 0; o >>= 1) s += __shfl_xor_sync(0xffffffffu, s, o);
    if ((tid & 31) == 0) reds[tid >> 5] = s;
    __syncthreads();
    s = reds[0];
#pragma unroll
    for (int i = 1; i < 8; i++) s += reds[i];
    float inv = 1.f / s;
#pragma unroll
    for (int i = 0; i < 4; i++) row[tid + i * 256] = v[i] * inv;
}

// ---------------- Bilinear 32->64 upsample (half-pixel), writes g_sum ----------------
__device__ __forceinline__ void up_weights(int y, int& ia, int& ib, float& wa, float& wb)
{
    int m = y >> 1;
    if ((y & 1) == 0) { ia = m - 1 < 0 ? 0 : m - 1; ib = m; wa = 0.25f; wb = 0.75f; }
    else { ia = m; ib = m + 1 > 31 ? 31 : m + 1; wa = 0.75f; wb = 0.25f; }
}

__global__ void upsample_kernel()
{
    int gid = blockIdx.x * 256 + threadIdx.x;  // B*4096*128 float4s
    int c4 = gid & 127;
    int n = (gid >> 7) & 4095;
    int b = gid >> 19;
    int y = n >> 6, x = n & 63;
    int ya, yb2; float wya, wyb;
    int xa, xb2; float wxa, wxb;
    up_weights(y, ya, yb2, wya, wyb);
    up_weights(x, xa, xb2, wxa, wxb);
    const float4* src = (const float4*)(g_out_hi + (size_t)b * NHI * Cch);
    float4 vaa = src[(size_t)(ya * 32 + xa) * 128 + c4];
    float4 vab = src[(size_t)(ya * 32 + xb2) * 128 + c4];
    float4 vba = src[(size_t)(yb2 * 32 + xa) * 128 + c4];
    float4 vbb = src[(size_t)(yb2 * 32 + xb2) * 128 + c4];
    float waa = wya * wxa, wab = wya * wxb, wba = wyb * wxa, wbb = wyb * wxb;
    float4 o;
    o.x = waa * vaa.x + wab * vab.x + wba * vba.x + wbb * vbb.x;
    o.y = waa * vaa.y + wab * vab.y + wba * vba.y + wbb * vbb.y;
    o.z = waa * vaa.z + wab * vab.z + wba * vba.z + wbb * vbb.z;
    o.w = waa * vaa.w + wab * vab.w + wba * vba.w + wbb * vbb.w;
    ((float4*)g_sum)[gid] = o;
}

// ---------------- Window gather: g_win[(b,w,t), p*128+q] = x[b, n(w,p), t*128+q] --------
__global__ void gather_win_kernel(const float* __restrict__ x)
{
    int gid = blockIdx.x * 256 + threadIdx.x;  // 32768*128 float4s
    int k4 = gid & 127;       // float4 index within 512-row
    int m = gid >> 7;
    int t = m & 3, w = (m >> 2) & 1023, b = m >> 12;
    int kp = k4 * 4;
    int p = kp >> 7, q = kp & 127;
    int wh = w >> 5, ww = w & 31;
    int i = p >> 1, j = p & 1;
    int n = (wh * 2 + i) * 64 + ww * 2 + j;
    const float4* src = (const float4*)(x + ((size_t)b * Ntok + n) * Cch + t * 128 + q);
    ((float4*)g_win)[gid] = src[0];
}

// ---------------- W_qkv permute for lo branch: W_lo[j, p*128+q] = W[j, q*4+p] ------------
__global__ void permw_kernel(const float* __restrict__ W)
{
    int gid = blockIdx.x * 256 + threadIdx.x;  // 1536*512
    if (gid >= 1536 * 512) return;
    int kp = gid & 511, j = gid >> 9;
    int p = kp >> 7, q = kp & 127;
    g_Wlo[gid] = W[j * 512 + q * 4 + p];
}

// ---------------- Lo-branch windowed attention (T=4), adds into g_sum -------------------
__global__ void lo_attn_kernel()
{
    __shared__ __align__(16) float sm[2][4 * 1536];
    int wp = threadIdx.x >> 5;
    int lane = threadIdx.x & 31;
    int widx = blockIdx.x * 2 + wp;  // 0..8191 = (b, w)
    int b = widx >> 10, w = widx & 1023;

    const float4* src4 = (const float4*)(g_qkv_lo + (size_t)widx * 4 * 1536);
    float4* sm4 = (float4*)sm[wp];
    for (int f = lane; f < 1536; f += 32) sm4[f] = src4[f];
    __syncwarp();

    int h = lane >> 2, ti = lane & 3;
    const float* base = sm[wp];
    const float4* q4 = (const float4*)(base + ti * 1536 + h * 64);
    float s[4];
#pragma unroll
    for (int tj = 0; tj < 4; tj++) {
        const float4* k4 = (const float4*)(base + tj * 1536 + 512 + h * 64);
        float acc = 0.f;
#pragma unroll
        for (int d = 0; d < 16; d++) {
            float4 a = q4[d], kk = k4[d];
            acc += a.x * kk.x + a.y * kk.y + a.z * kk.z + a.w * kk.w;
        }
        s[tj] = acc * 0.125f;
    }
    float mx = fmaxf(fmaxf(s[0], s[1]), fmaxf(s[2], s[3]));
    float p[4], sum = 0.f;
#pragma unroll
    for (int tj = 0; tj < 4; tj++) { p[tj] = __expf(s[tj] - mx); sum += p[tj]; }
    float inv = 1.f / sum;
#pragma unroll
    for (int tj = 0; tj < 4; tj++) p[tj] *= inv;

    int wh = w >> 5, ww = w & 31;
    int nout = (wh * 2 + (ti >> 1)) * 64 + ww * 2 + (ti & 1);
    float4* dst4 = (float4*)(g_sum + ((size_t)b * Ntok + nout) * Cch + h * 64);
    const float4* v0 = (const float4*)(base + 0 * 1536 + 1024 + h * 64);
    const float4* v1 = (const float4*)(base + 1 * 1536 + 1024 + h * 64);
    const float4* v2 = (const float4*)(base + 2 * 1536 + 1024 + h * 64);
    const float4* v3 = (const float4*)(base + 3 * 1536 + 1024 + h * 64);
#pragma unroll
    for (int d = 0; d < 16; d++) {
        float4 o = dst4[d];
        float4 a = v0[d], bb = v1[d], c = v2[d], e = v3[d];
        o.x += p[0] * a.x + p[1] * bb.x + p[2] * c.x + p[3] * e.x;
        o.y += p[0] * a.y + p[1] * bb.y + p[2] * c.y + p[3] * e.y;
        o.z += p[0] * a.z + p[1] * bb.z + p[2] * c.z + p[3] * e.z;
        o.w += p[0] * a.w + p[1] * bb.w + p[2] * c.w + p[3] * e.w;
        dst4[d] = o;
    }
}

// ---------------- Launch ----------------
extern "C" void kernel_launch(void* const* d_in, const int* in_sizes, int n_in,
                              void* d_out, int out_size)
{
    const float* x = (const float*)d_in[0];
    const float* Wqkv = (const float*)d_in[1];
    const float* Wproj = (const float*)d_in[2];
    const float* bproj = (const float*)d_in[3];
    float* out = (float*)d_out;

    float *xhi, *qkvhi, *S, *outhi, *win, *Wlo, *qkvlo, *sum;
    cudaGetSymbolAddress((void**)&xhi, g_xhi);
    cudaGetSymbolAddress((void**)&qkvhi, g_qkv_hi);
    cudaGetSymbolAddress((void**)&S, g_S);
    cudaGetSymbolAddress((void**)&outhi, g_out_hi);
    cudaGetSymbolAddress((void**)&win, g_win);
    cudaGetSymbolAddress((void**)&Wlo, g_Wlo);
    cudaGetSymbolAddress((void**)&qkvlo, g_qkv_lo);
    cudaGetSymbolAddress((void**)&sum, g_sum);

    // hi branch inputs
    pool_kernel<<<4096, 256>>>(x);
    // lo branch inputs (independent of hi)
    gather_win_kernel<<<16384, 256>>>(x);
    permw_kernel<<<(1536 * 512 + 255) / 256, 256>>>(Wqkv);

    // qkv_hi = x_hi @ W_qkv^T   [8192 x 1536], K=512
    sgemm_kernel<false, false><<<dim3(12, 64, 1), 256>>>(
        xhi, 512, 0, 0, Wqkv, 512, 0, 0, qkvhi, 1536, 0, 0, nullptr,
        8192, 1536, 512, 1.f, 1);

    // S = scale * Q @ K^T  batched over (b,h): M=N=1024, K=64
    sgemm_kernel<false, false><<<dim3(8, 8, 64), 256>>>(
        qkvhi, 1536, 1024LL * 1536, 64,
        qkvhi + 512, 1536, 1024LL * 1536, 64,
        S, 1024, 8LL * 1024 * 1024, 1024LL * 1024, nullptr,
        1024, 1024, 64, 0.125f, 8);

    softmax_kernel<<<65536, 256>>>(S);

    // O = P @ V  batched: M=1024, N=64, K=1024, B accessed transposed (V[j,d])
    sgemm_kernel<true, false><<<dim3(1, 8, 64), 256>>>(
        S, 1024, 8LL * 1024 * 1024, 1024LL * 1024,
        qkvhi + 1024, 1536, 1024LL * 1536, 64,
        outhi, 512, 1024LL * 512, 64, nullptr,
        1024, 64, 1024, 1.f, 8);

    upsample_kernel<<<16384, 256>>>();

    // qkv_lo = windows @ W_lo^T   [32768 x 1536], K=512
    sgemm_kernel<false, false><<<dim3(12, 256, 1), 256>>>(
        win, 512, 0, 0, Wlo, 512, 0, 0, qkvlo, 1536, 0, 0, nullptr,
        32768, 1536, 512, 1.f, 1);

    lo_attn_kernel<<<4096, 64>>>();

    // out = (hi_up + lo) @ W_proj^T + b_proj   [32768 x 512], K=512
    sgemm_kernel<false, true><<<dim3(4, 256, 1), 256>>>(
        sum, 512, 0, 0, Wproj, 512, 0, 0, out, 512, 0, 0, bproj,
        32768, 512, 512, 1.f, 1);
}

// round 9
// speedup vs baseline: 1.6168x; 1.6168x over previous
#include <cuda_runtime.h>
#include <cuda_bf16.h>
#include <cstdint>
#include <math.h>

// ================= Problem constants =================
#define Bc 8
#define Ntok 4096
#define Cch 512
#define NHI 1024

typedef __nv_bfloat16 bf16;

// ================= Scratch =================
__device__ float g_qkv_hi[(size_t)Bc * NHI * 1536];
__device__ float g_S[64ull * 1024 * 1024];
__device__ float g_out_hi[Bc * NHI * Cch];
__device__ float g_qkv_lo[(size_t)Bc * 1024 * 4 * 1536];
__device__ float g_sum[(size_t)Bc * Ntok * Cch];

__device__ bf16 g_xhih[Bc * NHI * Cch], g_xhil[Bc * NHI * Cch];
__device__ bf16 g_Wqh[1536 * 512], g_Wql[1536 * 512];
__device__ bf16 g_qh[(size_t)Bc * NHI * 1536], g_ql[(size_t)Bc * NHI * 1536];
__device__ bf16 g_Vth[64 * 64 * 1024], g_Vtl[64 * 64 * 1024];
__device__ bf16 g_Ph[64ull * 1024 * 1024], g_Pl[64ull * 1024 * 1024];
__device__ bf16 g_winh[(size_t)Bc * Ntok * Cch], g_winl[(size_t)Bc * Ntok * Cch];
__device__ bf16 g_Wloh[1536 * 512], g_Wlol[1536 * 512];
__device__ bf16 g_sumh[(size_t)Bc * Ntok * Cch], g_suml[(size_t)Bc * Ntok * Cch];
__device__ bf16 g_Wph[512 * 512], g_Wpl[512 * 512];

// ================= helpers =================
__device__ __forceinline__ uint32_t smem_to_u32(const void* p) {
    uint32_t a;
    asm("{ .reg .u64 t; cvta.to.shared.u64 t, %1; cvt.u32.u64 %0, t; }" : "=r"(a) : "l"(p));
    return a;
}

__device__ __forceinline__ void cp16(uint32_t s, const void* g) {
    asm volatile("cp.async.cg.shared.global [%0], [%1], 16;" :: "r"(s), "l"(g) : "memory");
}
__device__ __forceinline__ void cp_commit() {
    asm volatile("cp.async.commit_group;" ::: "memory");
}
template <int N>
__device__ __forceinline__ void cp_wait() {
    asm volatile("cp.async.wait_group %0;" :: "n"(N) : "memory");
}

__device__ __forceinline__ void ldm4(uint32_t* r, uint32_t addr) {
    asm volatile("ldmatrix.sync.aligned.m8n8.x4.shared.b16 {%0,%1,%2,%3}, [%4];"
        : "=r"(r[0]), "=r"(r[1]), "=r"(r[2]), "=r"(r[3]) : "r"(addr));
}

__device__ __forceinline__ void mma16816(float* c, const uint32_t* a, uint32_t b0, uint32_t b1) {
    asm volatile(
        "mma.sync.aligned.m16n8k16.row.col.f32.bf16.bf16.f32 "
        "{%0,%1,%2,%3}, {%4,%5,%6,%7}, {%8,%9}, {%0,%1,%2,%3};"
        : "+f"(c[0]), "+f"(c[1]), "+f"(c[2]), "+f"(c[3])
        : "r"(a[0]), "r"(a[1]), "r"(a[2]), "r"(a[3]), "r"(b0), "r"(b1));
}

// ================= split-bf16 GEMM via mma.sync (HMMA) =================
// C[bm..bm+127, bn..bn+NT-1] = alpha * sum_k (Ah+Al)[m,k]*(Bh+Bl)[n,k] (+bias)
// 3-pass: Ah*Bh + Ah*Bl + Al*Bh, fp32 accum.
// SMEM stage: Ah(16K) Al(16K) Bh(NT*128) Bl(NT*128), SW128 swizzle, 64-bf16 K chunks.
template <int NT, bool HASBIAS>
__global__ void __launch_bounds__(NT == 128 ? 256 : 128) mma_gemm(
    const bf16* __restrict__ Ah, const bf16* __restrict__ Al, int lda, long long sAb, long long sAh,
    const bf16* __restrict__ Bh, const bf16* __restrict__ Bl, int ldb, long long sBb, long long sBh,
    float* __restrict__ C, int ldc, long long sCb, long long sCh,
    const float* __restrict__ bias, int K, float alpha, int hdiv)
{
    constexpr int THREADS = (NT == 128) ? 256 : 128;
    constexpr int NWC = NT / 32;            // warp columns
    constexpr int BBYTES = NT * 128;        // B tile bytes per half
    constexpr int STAGE = 32768 + 2 * BBYTES;

    extern __shared__ __align__(1024) char smem[];
    uint32_t sb = smem_to_u32(smem);
    int tid = threadIdx.x, wid = tid >> 5, lane = tid & 31;
    int wr = wid / NWC, wc = wid % NWC;     // warp row (0/1: 64 rows), warp col (32 cols)

    int z = blockIdx.z, zb = z / hdiv, zh = z - zb * hdiv;
    long long offA = zb * sAb + zh * sAh;
    long long offB = zb * sBb + zh * sBh;
    Ah += offA; Al += offA; Bh += offB; Bl += offB;
    C += zb * sCb + zh * sCh;
    int bm = blockIdx.y * 128, bn = blockIdx.x * NT;

    float acc[4][4][4];
#pragma unroll
    for (int i = 0; i < 4; i++)
#pragma unroll
        for (int j = 0; j < 4; j++)
#pragma unroll
            for (int t = 0; t < 4; t++) acc[i][j][t] = 0.f;

    int NC = K >> 6;

    // ---- stage loader ----
    auto issue = [&](int c) {
        int s = c & 1;
        int k0 = c * 64;
        uint32_t sbase = sb + s * STAGE;
#pragma unroll
        for (int i = 0; i < 1024 / THREADS; i++) {
            int idx = tid + i * THREADS;
            int row = idx >> 3, c16 = idx & 7;
            uint32_t d = (uint32_t)(row * 128 + ((c16 ^ (row & 7)) << 4));
            size_t go = (size_t)(bm + row) * lda + k0 + c16 * 8;
            cp16(sbase + d, Ah + go);
            cp16(sbase + 16384 + d, Al + go);
        }
#pragma unroll
        for (int i = 0; i < (NT * 8) / THREADS; i++) {
            int idx = tid + i * THREADS;
            int row = idx >> 3, c16 = idx & 7;
            uint32_t d = (uint32_t)(row * 128 + ((c16 ^ (row & 7)) << 4));
            size_t go = (size_t)(bn + row) * ldb + k0 + c16 * 8;
            cp16(sbase + 32768 + d, Bh + go);
            cp16(sbase + 32768 + BBYTES + d, Bl + go);
        }
        cp_commit();
    };

    issue(0);

    for (int c = 0; c < NC; c++) {
        if (c + 1 < NC) { issue(c + 1); cp_wait<1>(); }
        else            { cp_wait<0>(); }
        __syncthreads();

        uint32_t Ab = sb + (c & 1) * STAGE;
        uint32_t Bb = Ab + 32768;
#pragma unroll
        for (int ks = 0; ks < 4; ks++) {
            uint32_t ah[4][4], al[4][4];
#pragma unroll
            for (int i = 0; i < 4; i++) {
                int row = wr * 64 + i * 16 + (lane & 15);
                int c16 = ks * 2 + (lane >> 4);
                uint32_t ad = (uint32_t)(row * 128 + ((c16 ^ (row & 7)) << 4));
                ldm4(ah[i], Ab + ad);
                ldm4(al[i], Ab + 16384 + ad);
            }
            uint32_t bh[8], bl[8];
#pragma unroll
            for (int j2 = 0; j2 < 2; j2++) {
                int nrow = wc * 32 + j2 * 16 + ((lane >> 4) << 3) + (lane & 7);
                int c16 = ks * 2 + ((lane >> 3) & 1);
                uint32_t bd = (uint32_t)(nrow * 128 + ((c16 ^ (nrow & 7)) << 4));
                ldm4(&bh[j2 * 4], Bb + bd);
                ldm4(&bl[j2 * 4], Bb + BBYTES + bd);
            }
#pragma unroll
            for (int i = 0; i < 4; i++)
#pragma unroll
                for (int j = 0; j < 4; j++) {
                    mma16816(acc[i][j], ah[i], bh[j * 2], bh[j * 2 + 1]);
                    mma16816(acc[i][j], ah[i], bl[j * 2], bl[j * 2 + 1]);
                    mma16816(acc[i][j], al[i], bh[j * 2], bh[j * 2 + 1]);
                }
        }
        __syncthreads();
    }

    // ---- epilogue ----
    int r = lane >> 2, cp2 = (lane & 3) * 2;
#pragma unroll
    for (int i = 0; i < 4; i++) {
        int row = bm + wr * 64 + i * 16 + r;
#pragma unroll
        for (int j = 0; j < 4; j++) {
            int col = bn + wc * 32 + j * 8 + cp2;
            float2 v0, v1;
            v0.x = acc[i][j][0] * alpha; v0.y = acc[i][j][1] * alpha;
            v1.x = acc[i][j][2] * alpha; v1.y = acc[i][j][3] * alpha;
            if (HASBIAS) {
                float b0 = bias[col], b1 = bias[col + 1];
                v0.x += b0; v0.y += b1; v1.x += b0; v1.y += b1;
            }
            *(float2*)&C[(size_t)row * ldc + col] = v0;
            *(float2*)&C[(size_t)(row + 8) * ldc + col] = v1;
        }
    }
}

// ================= split helpers =================
__device__ __forceinline__ void split4(float4 v, bf16* h, bf16* l, size_t base)
{
    float a[4] = { v.x, v.y, v.z, v.w };
    bf16 hh[4], ll[4];
#pragma unroll
    for (int i = 0; i < 4; i++) {
        hh[i] = __float2bfloat16(a[i]);
        ll[i] = __float2bfloat16(a[i] - __bfloat162float(hh[i]));
    }
    *(uint2*)(h + base) = *(uint2*)hh;
    *(uint2*)(l + base) = *(uint2*)ll;
}

__global__ void split_generic(const float4* __restrict__ src, bf16* __restrict__ h,
                              bf16* __restrict__ l, int n4)
{
    int gid = blockIdx.x * 256 + threadIdx.x;
    if (gid >= n4) return;
    split4(src[gid], h, l, (size_t)gid * 4);
}

__global__ void pool_split(const float* __restrict__ x)
{
    int gid = blockIdx.x * 256 + threadIdx.x;  // B*1024*128
    int c4 = gid & 127;
    int hw = (gid >> 7) & 1023;
    int b = gid >> 17;
    int wh = hw >> 5, ww = hw & 31;
    int n0 = (wh * 2) * 64 + ww * 2;
    const float4* xb = (const float4*)(x + (size_t)b * Ntok * Cch);
    float4 a = xb[(size_t)n0 * 128 + c4];
    float4 bv = xb[(size_t)(n0 + 1) * 128 + c4];
    float4 c = xb[(size_t)(n0 + 64) * 128 + c4];
    float4 d = xb[(size_t)(n0 + 65) * 128 + c4];
    float4 o;
    o.x = (a.x + bv.x + c.x + d.x) * 0.25f;
    o.y = (a.y + bv.y + c.y + d.y) * 0.25f;
    o.z = (a.z + bv.z + c.z + d.z) * 0.25f;
    o.w = (a.w + bv.w + c.w + d.w) * 0.25f;
    split4(o, g_xhih, g_xhil, (size_t)gid * 4);
}

__global__ void gather_win_split(const float* __restrict__ x)
{
    int gid = blockIdx.x * 256 + threadIdx.x;  // 32768*128
    int k4 = gid & 127;
    int m = gid >> 7;
    int t = m & 3, w = (m >> 2) & 1023, b = m >> 12;
    int kp = k4 * 4;
    int p = kp >> 7, q = kp & 127;
    int wh = w >> 5, ww = w & 31;
    int i = p >> 1, j = p & 1;
    int n = (wh * 2 + i) * 64 + ww * 2 + j;
    float4 v = *(const float4*)(x + ((size_t)b * Ntok + n) * Cch + t * 128 + q);
    split4(v, g_winh, g_winl, (size_t)gid * 4);
}

__global__ void permw_split(const float* __restrict__ W)
{
    int gid = blockIdx.x * 256 + threadIdx.x;  // 1536*512
    if (gid >= 1536 * 512) return;
    int kp = gid & 511, j = gid >> 9;
    int p = kp >> 7, q = kp & 127;
    float v = W[j * 512 + q * 4 + p];
    bf16 h = __float2bfloat16(v);
    g_Wloh[gid] = h;
    g_Wlol[gid] = __float2bfloat16(v - __bfloat162float(h));
}

__global__ void vt_split()
{
    int gid = blockIdx.x * 256 + threadIdx.x;  // 64*64*1024
    int j = gid & 1023;
    int d = (gid >> 10) & 63;
    int bh = gid >> 16;
    int b = bh >> 3, h2 = bh & 7;
    float v = g_qkv_hi[((size_t)b * 1024 + j) * 1536 + 1024 + h2 * 64 + d];
    bf16 h = __float2bfloat16(v);
    g_Vth[gid] = h;
    g_Vtl[gid] = __float2bfloat16(v - __bfloat162float(h));
}

__global__ void softmax_split(const float* __restrict__ S)
{
    const float* row = S + (size_t)blockIdx.x * 1024;
    size_t obase = (size_t)blockIdx.x * 1024;
    int tid = threadIdx.x;
    __shared__ float redm[8], reds[8];
    float v[4];
    float mx = -1e30f;
#pragma unroll
    for (int i = 0; i < 4; i++) { v[i] = row[tid + i * 256]; mx = fmaxf(mx, v[i]); }
#pragma unroll
    for (int o = 16; o > 0; o >>= 1) mx = fmaxf(mx, __shfl_xor_sync(0xffffffffu, mx, o));
    if ((tid & 31) == 0) redm[tid >> 5] = mx;
    __syncthreads();
    mx = redm[0];
#pragma unroll
    for (int i = 1; i < 8; i++) mx = fmaxf(mx, redm[i]);
    float s = 0.f;
#pragma unroll
    for (int i = 0; i < 4; i++) { v[i] = __expf(v[i] - mx); s += v[i]; }
#pragma unroll
    for (int o = 16; o > 0; o >>= 1) s += __shfl_xor_sync(0xffffffffu, s, o);
    if ((tid & 31) == 0) reds[tid >> 5] = s;
    __syncthreads();
    s = reds[0];
#pragma unroll
    for (int i = 1; i < 8; i++) s += reds[i];
    float inv = 1.f / s;
#pragma unroll
    for (int i = 0; i < 4; i++) {
        float p = v[i] * inv;
        bf16 h = __float2bfloat16(p);
        g_Ph[obase + tid + i * 256] = h;
        g_Pl[obase + tid + i * 256] = __float2bfloat16(p - __bfloat162float(h));
    }
}

__device__ __forceinline__ void up_weights(int y, int& ia, int& ib, float& wa, float& wb)
{
    int m = y >> 1;
    if ((y & 1) == 0) { ia = m - 1 < 0 ? 0 : m - 1; ib = m; wa = 0.25f; wb = 0.75f; }
    else { ia = m; ib = m + 1 > 31 ? 31 : m + 1; wa = 0.75f; wb = 0.25f; }
}

__global__ void upsample_kernel()
{
    int gid = blockIdx.x * 256 + threadIdx.x;
    int c4 = gid & 127;
    int n = (gid >> 7) & 4095;
    int b = gid >> 19;
    int y = n >> 6, x = n & 63;
    int ya, yb2; float wya, wyb;
    int xa, xb2; float wxa, wxb;
    up_weights(y, ya, yb2, wya, wyb);
    up_weights(x, xa, xb2, wxa, wxb);
    const float4* src = (const float4*)(g_out_hi + (size_t)b * NHI * Cch);
    float4 vaa = src[(size_t)(ya * 32 + xa) * 128 + c4];
    float4 vab = src[(size_t)(ya * 32 + xb2) * 128 + c4];
    float4 vba = src[(size_t)(yb2 * 32 + xa) * 128 + c4];
    float4 vbb = src[(size_t)(yb2 * 32 + xb2) * 128 + c4];
    float waa = wya * wxa, wab = wya * wxb, wba = wyb * wxa, wbb = wyb * wxb;
    float4 o;
    o.x = waa * vaa.x + wab * vab.x + wba * vba.x + wbb * vbb.x;
    o.y = waa * vaa.y + wab * vab.y + wba * vba.y + wbb * vbb.y;
    o.z = waa * vaa.z + wab * vab.z + wba * vba.z + wbb * vbb.z;
    o.w = waa * vaa.w + wab * vab.w + wba * vba.w + wbb * vbb.w;
    ((float4*)g_sum)[gid] = o;
}

__global__ void lo_attn_kernel()
{
    __shared__ __align__(16) float sm[2][4 * 1536];
    int wp = threadIdx.x >> 5;
    int lane = threadIdx.x & 31;
    int widx = blockIdx.x * 2 + wp;
    int b = widx >> 10, w = widx & 1023;

    const float4* src4 = (const float4*)(g_qkv_lo + (size_t)widx * 4 * 1536);
    float4* sm4 = (float4*)sm[wp];
    for (int f = lane; f < 1536; f += 32) sm4[f] = src4[f];
    __syncwarp();

    int h = lane >> 2, ti = lane & 3;
    const float* base = sm[wp];
    const float4* q4 = (const float4*)(base + ti * 1536 + h * 64);
    float s[4];
#pragma unroll
    for (int tj = 0; tj < 4; tj++) {
        const float4* k4 = (const float4*)(base + tj * 1536 + 512 + h * 64);
        float acc = 0.f;
#pragma unroll
        for (int d = 0; d < 16; d++) {
            float4 a = q4[d], kk = k4[d];
            acc += a.x * kk.x + a.y * kk.y + a.z * kk.z + a.w * kk.w;
        }
        s[tj] = acc * 0.125f;
    }
    float mx = fmaxf(fmaxf(s[0], s[1]), fmaxf(s[2], s[3]));
    float p[4], sum = 0.f;
#pragma unroll
    for (int tj = 0; tj < 4; tj++) { p[tj] = __expf(s[tj] - mx); sum += p[tj]; }
    float inv = 1.f / sum;
#pragma unroll
    for (int tj = 0; tj < 4; tj++) p[tj] *= inv;

    int wh = w >> 5, ww = w & 31;
    int nout = (wh * 2 + (ti >> 1)) * 64 + ww * 2 + (ti & 1);
    float4* dst4 = (float4*)(g_sum + ((size_t)b * Ntok + nout) * Cch + h * 64);
    const float4* v0 = (const float4*)(base + 0 * 1536 + 1024 + h * 64);
    const float4* v1 = (const float4*)(base + 1 * 1536 + 1024 + h * 64);
    const float4* v2 = (const float4*)(base + 2 * 1536 + 1024 + h * 64);
    const float4* v3 = (const float4*)(base + 3 * 1536 + 1024 + h * 64);
#pragma unroll
    for (int d = 0; d < 16; d++) {
        float4 o = dst4[d];
        float4 a = v0[d], bb = v1[d], c = v2[d], e = v3[d];
        o.x += p[0] * a.x + p[1] * bb.x + p[2] * c.x + p[3] * e.x;
        o.y += p[0] * a.y + p[1] * bb.y + p[2] * c.y + p[3] * e.y;
        o.z += p[0] * a.z + p[1] * bb.z + p[2] * c.z + p[3] * e.z;
        o.w += p[0] * a.w + p[1] * bb.w + p[2] * c.w + p[3] * e.w;
        dst4[d] = o;
    }
}

// ================= Launch =================
extern "C" void kernel_launch(void* const* d_in, const int* in_sizes, int n_in,
                              void* d_out, int out_size)
{
    const float* x = (const float*)d_in[0];
    const float* Wqkv = (const float*)d_in[1];
    const float* Wproj = (const float*)d_in[2];
    const float* bproj = (const float*)d_in[3];
    float* out = (float*)d_out;

    float *qkvhi, *S, *outhi, *qkvlo, *sum;
    bf16 *xhih, *xhil, *Wqh, *Wql, *qh, *ql, *Vth, *Vtl, *Ph, *Pl;
    bf16 *winh, *winl, *Wloh, *Wlol, *sumh, *suml, *Wph, *Wpl;
    cudaGetSymbolAddress((void**)&qkvhi, g_qkv_hi);
    cudaGetSymbolAddress((void**)&S, g_S);
    cudaGetSymbolAddress((void**)&outhi, g_out_hi);
    cudaGetSymbolAddress((void**)&qkvlo, g_qkv_lo);
    cudaGetSymbolAddress((void**)&sum, g_sum);
    cudaGetSymbolAddress((void**)&xhih, g_xhih);
    cudaGetSymbolAddress((void**)&xhil, g_xhil);
    cudaGetSymbolAddress((void**)&Wqh, g_Wqh);
    cudaGetSymbolAddress((void**)&Wql, g_Wql);
    cudaGetSymbolAddress((void**)&qh, g_qh);
    cudaGetSymbolAddress((void**)&ql, g_ql);
    cudaGetSymbolAddress((void**)&Vth, g_Vth);
    cudaGetSymbolAddress((void**)&Vtl, g_Vtl);
    cudaGetSymbolAddress((void**)&Ph, g_Ph);
    cudaGetSymbolAddress((void**)&Pl, g_Pl);
    cudaGetSymbolAddress((void**)&winh, g_winh);
    cudaGetSymbolAddress((void**)&winl, g_winl);
    cudaGetSymbolAddress((void**)&Wloh, g_Wloh);
    cudaGetSymbolAddress((void**)&Wlol, g_Wlol);
    cudaGetSymbolAddress((void**)&sumh, g_sumh);
    cudaGetSymbolAddress((void**)&suml, g_suml);
    cudaGetSymbolAddress((void**)&Wph, g_Wph);
    cudaGetSymbolAddress((void**)&Wpl, g_Wpl);

    const int SMEM128 = 2 * (32768 + 2 * 128 * 128);  // 131072
    const int SMEM64  = 2 * (32768 + 2 * 64 * 128);   //  98304
    cudaFuncSetAttribute(mma_gemm<128, false>, cudaFuncAttributeMaxDynamicSharedMemorySize, SMEM128);
    cudaFuncSetAttribute(mma_gemm<64, false>,  cudaFuncAttributeMaxDynamicSharedMemorySize, SMEM64);
    cudaFuncSetAttribute(mma_gemm<128, true>,  cudaFuncAttributeMaxDynamicSharedMemorySize, SMEM128);

    // input prep
    pool_split<<<4096, 256>>>(x);
    split_generic<<<768, 256>>>((const float4*)Wqkv, Wqh, Wql, 196608);
    gather_win_split<<<16384, 256>>>(x);
    permw_split<<<3072, 256>>>(Wqkv);
    split_generic<<<256, 256>>>((const float4*)Wproj, Wph, Wpl, 65536);

    // qkv_hi = x_hi @ W_qkv^T : [8192 x 1536], K=512
    mma_gemm<128, false><<<dim3(12, 64, 1), 256, SMEM128>>>(
        xhih, xhil, 512, 0, 0, Wqh, Wql, 512, 0, 0,
        qkvhi, 1536, 0, 0, nullptr, 512, 1.f, 1);

    split_generic<<<12288, 256>>>((const float4*)qkvhi, qh, ql, 3145728);
    vt_split<<<16384, 256>>>();

    // S = 0.125 * Q K^T, batched (b,h): M=N=1024, K=64
    mma_gemm<128, false><<<dim3(8, 8, 64), 256, SMEM128>>>(
        qh, ql, 1536, 1024LL * 1536, 64,
        qh + 512, ql + 512, 1536, 1024LL * 1536, 64,
        S, 1024, 8LL * 1024 * 1024, 1024LL * 1024, nullptr, 64, 0.125f, 8);

    softmax_split<<<65536, 256>>>(S);

    // O = P @ Vt^T : M=1024, N=64, K=1024, batched
    mma_gemm<64, false><<<dim3(1, 8, 64), 128, SMEM64>>>(
        Ph, Pl, 1024, 8LL * 1024 * 1024, 1024LL * 1024,
        Vth, Vtl, 1024, 8LL * 64 * 1024, 64LL * 1024,
        outhi, 512, 1024LL * 512, 64, nullptr, 1024, 1.f, 8);

    upsample_kernel<<<16384, 256>>>();

    // qkv_lo = windows @ W_lo^T : [32768 x 1536], K=512
    mma_gemm<128, false><<<dim3(12, 256, 1), 256, SMEM128>>>(
        winh, winl, 512, 0, 0, Wloh, Wlol, 512, 0, 0,
        qkvlo, 1536, 0, 0, nullptr, 512, 1.f, 1);

    lo_attn_kernel<<<4096, 64>>>();

    split_generic<<<16384, 256>>>((const float4*)sum, sumh, suml, 4194304);

    // out = (hi_up + lo) @ W_proj^T + b : [32768 x 512], K=512
    mma_gemm<128, true><<<dim3(4, 256, 1), 256, SMEM128>>>(
        sumh, suml, 512, 0, 0, Wph, Wpl, 512, 0, 0,
        out, 512, 0, 0, bproj, 512, 1.f, 1);
}

// round 11
// speedup vs baseline: 2.9785x; 1.8422x over previous
#include <cuda_runtime.h>
#include <cuda_bf16.h>
#include <cstdint>
#include <math.h>

// ================= Problem constants =================
#define Bc 8
#define Ntok 4096
#define Cch 512
#define NHI 1024

typedef __nv_bfloat16 bf16;

// ================= Scratch =================
__device__ float g_out_hi[Bc * NHI * Cch];
__device__ float g_qkv_lo[(size_t)Bc * 1024 * 4 * 1536];
__device__ float g_sum[(size_t)Bc * Ntok * Cch];

__device__ bf16 g_xhih[Bc * NHI * Cch], g_xhil[Bc * NHI * Cch];
__device__ bf16 g_Wqh[1536 * 512], g_Wql[1536 * 512];
__device__ bf16 g_qh[(size_t)Bc * NHI * 1536], g_ql[(size_t)Bc * NHI * 1536];
__device__ bf16 g_winh[(size_t)Bc * Ntok * Cch], g_winl[(size_t)Bc * Ntok * Cch];
__device__ bf16 g_Wloh[1536 * 512], g_Wlol[1536 * 512];
__device__ bf16 g_sumh[(size_t)Bc * Ntok * Cch], g_suml[(size_t)Bc * Ntok * Cch];
__device__ bf16 g_Wph[512 * 512], g_Wpl[512 * 512];

// ================= helpers =================
__device__ __forceinline__ uint32_t smem_to_u32(const void* p) {
    uint32_t a;
    asm("{ .reg .u64 t; cvta.to.shared.u64 t, %1; cvt.u32.u64 %0, t; }" : "=r"(a) : "l"(p));
    return a;
}

__device__ __forceinline__ void cp16(uint32_t s, const void* g) {
    asm volatile("cp.async.cg.shared.global [%0], [%1], 16;" :: "r"(s), "l"(g) : "memory");
}
__device__ __forceinline__ void cp_commit() {
    asm volatile("cp.async.commit_group;" ::: "memory");
}
template <int N>
__device__ __forceinline__ void cp_wait() {
    asm volatile("cp.async.wait_group %0;" :: "n"(N) : "memory");
}

__device__ __forceinline__ void ldm4(uint32_t* r, uint32_t addr) {
    asm volatile("ldmatrix.sync.aligned.m8n8.x4.shared.b16 {%0,%1,%2,%3}, [%4];"
        : "=r"(r[0]), "=r"(r[1]), "=r"(r[2]), "=r"(r[3]) : "r"(addr));
}
__device__ __forceinline__ void ldm4t(uint32_t* r, uint32_t addr) {
    asm volatile("ldmatrix.sync.aligned.m8n8.x4.trans.shared.b16 {%0,%1,%2,%3}, [%4];"
        : "=r"(r[0]), "=r"(r[1]), "=r"(r[2]), "=r"(r[3]) : "r"(addr));
}

__device__ __forceinline__ void mma16816(float* c, const uint32_t* a, uint32_t b0, uint32_t b1) {
    asm volatile(
        "mma.sync.aligned.m16n8k16.row.col.f32.bf16.bf16.f32 "
        "{%0,%1,%2,%3}, {%4,%5,%6,%7}, {%8,%9}, {%0,%1,%2,%3};"
        : "+f"(c[0]), "+f"(c[1]), "+f"(c[2]), "+f"(c[3])
        : "r"(a[0]), "r"(a[1]), "r"(a[2]), "r"(a[3]), "r"(b0), "r"(b1));
}

// split two floats into packed-bf16 hi and lo words
__device__ __forceinline__ void psplit2(float x, float y, uint32_t& hp, uint32_t& lp) {
    bf16 hx = __float2bfloat16(x), hy = __float2bfloat16(y);
    bf16 lx = __float2bfloat16(x - __bfloat162float(hx));
    bf16 ly = __float2bfloat16(y - __bfloat162float(hy));
    hp = (uint32_t)*(uint16_t*)&hx | ((uint32_t)*(uint16_t*)&hy << 16);
    lp = (uint32_t)*(uint16_t*)&lx | ((uint32_t)*(uint16_t*)&ly << 16);
}

// ================= split-bf16 GEMM via mma.sync =================
// OUTMODE: 0 = fp32 C, 1 = fp32 C + bias, 2 = split bf16 (Ch, Cl)
template <int NT, int OUTMODE>
__global__ void __launch_bounds__(NT == 128 ? 256 : 128) mma_gemm(
    const bf16* __restrict__ Ah, const bf16* __restrict__ Al, int lda, long long sAb, long long sAh,
    const bf16* __restrict__ Bh, const bf16* __restrict__ Bl, int ldb, long long sBb, long long sBh,
    float* __restrict__ C, bf16* __restrict__ Ch, bf16* __restrict__ Cl,
    int ldc, long long sCb, long long sCh,
    const float* __restrict__ bias, int K, float alpha, int hdiv)
{
    constexpr int THREADS = (NT == 128) ? 256 : 128;
    constexpr int NWC = NT / 32;
    constexpr int BBYTES = NT * 128;
    constexpr int STAGE = 32768 + 2 * BBYTES;

    extern __shared__ __align__(1024) char smem[];
    uint32_t sb = smem_to_u32(smem);
    int tid = threadIdx.x, wid = tid >> 5, lane = tid & 31;
    int wr = wid / NWC, wc = wid % NWC;

    int z = blockIdx.z, zb = z / hdiv, zh = z - zb * hdiv;
    long long offA = zb * sAb + zh * sAh;
    long long offB = zb * sBb + zh * sBh;
    Ah += offA; Al += offA; Bh += offB; Bl += offB;
    long long offC = zb * sCb + zh * sCh;
    int bm = blockIdx.y * 128, bn = blockIdx.x * NT;

    float acc[4][4][4];
#pragma unroll
    for (int i = 0; i < 4; i++)
#pragma unroll
        for (int j = 0; j < 4; j++)
#pragma unroll
            for (int t = 0; t < 4; t++) acc[i][j][t] = 0.f;

    int NC = K >> 6;

    auto issue = [&](int c) {
        int s = c & 1;
        int k0 = c * 64;
        uint32_t sbase = sb + s * STAGE;
#pragma unroll
        for (int i = 0; i < 1024 / THREADS; i++) {
            int idx = tid + i * THREADS;
            int row = idx >> 3, c16 = idx & 7;
            uint32_t d = (uint32_t)(row * 128 + ((c16 ^ (row & 7)) << 4));
            size_t go = (size_t)(bm + row) * lda + k0 + c16 * 8;
            cp16(sbase + d, Ah + go);
            cp16(sbase + 16384 + d, Al + go);
        }
#pragma unroll
        for (int i = 0; i < (NT * 8) / THREADS; i++) {
            int idx = tid + i * THREADS;
            int row = idx >> 3, c16 = idx & 7;
            uint32_t d = (uint32_t)(row * 128 + ((c16 ^ (row & 7)) << 4));
            size_t go = (size_t)(bn + row) * ldb + k0 + c16 * 8;
            cp16(sbase + 32768 + d, Bh + go);
            cp16(sbase + 32768 + BBYTES + d, Bl + go);
        }
        cp_commit();
    };

    issue(0);

    for (int c = 0; c < NC; c++) {
        if (c + 1 < NC) { issue(c + 1); cp_wait<1>(); }
        else            { cp_wait<0>(); }
        __syncthreads();

        uint32_t Ab = sb + (c & 1) * STAGE;
        uint32_t Bb = Ab + 32768;
#pragma unroll
        for (int ks = 0; ks < 4; ks++) {
            uint32_t ah[4][4], al[4][4];
#pragma unroll
            for (int i = 0; i < 4; i++) {
                int row = wr * 64 + i * 16 + (lane & 15);
                int c16 = ks * 2 + (lane >> 4);
                uint32_t ad = (uint32_t)(row * 128 + ((c16 ^ (row & 7)) << 4));
                ldm4(ah[i], Ab + ad);
                ldm4(al[i], Ab + 16384 + ad);
            }
            uint32_t bh[8], bl[8];
#pragma unroll
            for (int j2 = 0; j2 < 2; j2++) {
                int nrow = wc * 32 + j2 * 16 + ((lane >> 4) << 3) + (lane & 7);
                int c16 = ks * 2 + ((lane >> 3) & 1);
                uint32_t bd = (uint32_t)(nrow * 128 + ((c16 ^ (nrow & 7)) << 4));
                ldm4(&bh[j2 * 4], Bb + bd);
                ldm4(&bl[j2 * 4], Bb + BBYTES + bd);
            }
#pragma unroll
            for (int i = 0; i < 4; i++)
#pragma unroll
                for (int j = 0; j < 4; j++) {
                    mma16816(acc[i][j], ah[i], bh[j * 2], bh[j * 2 + 1]);
                    mma16816(acc[i][j], ah[i], bl[j * 2], bl[j * 2 + 1]);
                    mma16816(acc[i][j], al[i], bh[j * 2], bh[j * 2 + 1]);
                }
        }
        __syncthreads();
    }

    int r = lane >> 2, cp2 = (lane & 3) * 2;
#pragma unroll
    for (int i = 0; i < 4; i++) {
        int row = bm + wr * 64 + i * 16 + r;
#pragma unroll
        for (int j = 0; j < 4; j++) {
            int col = bn + wc * 32 + j * 8 + cp2;
            float2 v0, v1;
            v0.x = acc[i][j][0] * alpha; v0.y = acc[i][j][1] * alpha;
            v1.x = acc[i][j][2] * alpha; v1.y = acc[i][j][3] * alpha;
            if (OUTMODE == 1) {
                float b0 = bias[col], b1 = bias[col + 1];
                v0.x += b0; v0.y += b1; v1.x += b0; v1.y += b1;
            }
            if (OUTMODE == 2) {
                uint32_t hp, lp;
                psplit2(v0.x, v0.y, hp, lp);
                *(uint32_t*)&Ch[(offC + (size_t)row * ldc + col)] = hp;
                *(uint32_t*)&Cl[(offC + (size_t)row * ldc + col)] = lp;
                psplit2(v1.x, v1.y, hp, lp);
                *(uint32_t*)&Ch[(offC + (size_t)(row + 8) * ldc + col)] = hp;
                *(uint32_t*)&Cl[(offC + (size_t)(row + 8) * ldc + col)] = lp;
            } else {
                *(float2*)&C[offC + (size_t)row * ldc + col] = v0;
                *(float2*)&C[offC + (size_t)(row + 8) * ldc + col] = v1;
            }
        }
    }
}

// ================= FlashAttention-2 style hi-branch attention =================
// grid (8 mtiles, 64 bh), 128 threads. Q/K/V from split qh/ql [(b*1024+n)*1536 + sel + h*64 + d]
// out_hi[(b*1024+n)*512 + h*64 + d] fp32.
__global__ void __launch_bounds__(128) flash_hi(
    const bf16* __restrict__ Qh, const bf16* __restrict__ Ql, float* __restrict__ outhi)
{
    extern __shared__ __align__(1024) char smem[];
    uint32_t sb = smem_to_u32(smem);
    const uint32_t sQh = sb, sQl = sb + 16384;
    int tid = threadIdx.x, wid = tid >> 5, lane = tid & 31;
    int mtile = blockIdx.x, bh = blockIdx.y;
    int b = bh >> 3, h = bh & 7;

    size_t qbase = ((size_t)(b * 1024) + mtile * 128) * 1536 + h * 64;
    // Q tile 128x64 (h/l) -> group 0
#pragma unroll
    for (int i = 0; i < 8; i++) {
        int idx = tid + i * 128;
        int row = idx >> 3, c16 = idx & 7;
        uint32_t d = (uint32_t)(row * 128 + ((c16 ^ (row & 7)) << 4));
        size_t go = qbase + (size_t)row * 1536 + c16 * 8;
        cp16(sQh + d, Qh + go);
        cp16(sQl + d, Ql + go);
    }
    cp_commit();

    auto issueKV = [&](int t) {
        uint32_t kb = sb + 32768 + (t & 1) * 32768;
        size_t kbase = ((size_t)(b * 1024) + t * 64) * 1536 + 512 + h * 64;
#pragma unroll
        for (int i = 0; i < 4; i++) {
            int idx = tid + i * 128;
            int row = idx >> 3, c16 = idx & 7;
            uint32_t d = (uint32_t)(row * 128 + ((c16 ^ (row & 7)) << 4));
            size_t go = kbase + (size_t)row * 1536 + c16 * 8;
            cp16(kb + d, Qh + go);                    // Kh
            cp16(kb + 8192 + d, Ql + go);             // Kl
            cp16(kb + 16384 + d, Qh + go + 512);      // Vh
            cp16(kb + 24576 + d, Ql + go + 512);      // Vl
        }
        cp_commit();
    };
    issueKV(0);
    issueKV(1);

    int rbase = wid * 32;
    float o[2][8][4];
    float mrow[2][2], lrow[2][2];
#pragma unroll
    for (int mi = 0; mi < 2; mi++) {
#pragma unroll
        for (int j = 0; j < 8; j++)
#pragma unroll
            for (int e = 0; e < 4; e++) o[mi][j][e] = 0.f;
        mrow[mi][0] = -INFINITY; mrow[mi][1] = -INFINITY;
        lrow[mi][0] = 0.f; lrow[mi][1] = 0.f;
    }

    for (int t = 0; t < 16; t++) {
        if (t < 15) cp_wait<1>(); else cp_wait<0>();
        __syncthreads();
        uint32_t kb = sb + 32768 + (t & 1) * 32768;

        // ---- S = Q K^T (3-pass) ----
        float s[2][8][4];
#pragma unroll
        for (int mi = 0; mi < 2; mi++)
#pragma unroll
            for (int j = 0; j < 8; j++)
#pragma unroll
                for (int e = 0; e < 4; e++) s[mi][j][e] = 0.f;

#pragma unroll
        for (int kd = 0; kd < 4; kd++) {
            uint32_t aqh[2][4], aql[2][4];
#pragma unroll
            for (int mi = 0; mi < 2; mi++) {
                int row = rbase + mi * 16 + (lane & 15);
                int c16 = kd * 2 + (lane >> 4);
                uint32_t ad = (uint32_t)(row * 128 + ((c16 ^ (row & 7)) << 4));
                ldm4(aqh[mi], sQh + ad);
                ldm4(aql[mi], sQl + ad);
            }
            uint32_t bkh[16], bkl[16];
#pragma unroll
            for (int j2 = 0; j2 < 4; j2++) {
                int nrow = j2 * 16 + ((lane >> 4) << 3) + (lane & 7);
                int c16 = kd * 2 + ((lane >> 3) & 1);
                uint32_t bd = (uint32_t)(nrow * 128 + ((c16 ^ (nrow & 7)) << 4));
                ldm4(&bkh[j2 * 4], kb + bd);
                ldm4(&bkl[j2 * 4], kb + 8192 + bd);
            }
#pragma unroll
            for (int mi = 0; mi < 2; mi++)
#pragma unroll
                for (int j = 0; j < 8; j++) {
                    mma16816(s[mi][j], aqh[mi], bkh[j * 2], bkh[j * 2 + 1]);
                    mma16816(s[mi][j], aqh[mi], bkl[j * 2], bkl[j * 2 + 1]);
                    mma16816(s[mi][j], aql[mi], bkh[j * 2], bkh[j * 2 + 1]);
                }
        }

        // ---- online softmax (scale 0.125) ----
#pragma unroll
        for (int mi = 0; mi < 2; mi++)
#pragma unroll
            for (int j = 0; j < 8; j++)
#pragma unroll
                for (int e = 0; e < 4; e++) s[mi][j][e] *= 0.125f;

#pragma unroll
        for (int mi = 0; mi < 2; mi++)
#pragma unroll
            for (int hf = 0; hf < 2; hf++) {
                float tm = -INFINITY;
#pragma unroll
                for (int j = 0; j < 8; j++)
                    tm = fmaxf(tm, fmaxf(s[mi][j][hf * 2], s[mi][j][hf * 2 + 1]));
                tm = fmaxf(tm, __shfl_xor_sync(0xffffffffu, tm, 1));
                tm = fmaxf(tm, __shfl_xor_sync(0xffffffffu, tm, 2));
                float mnew = fmaxf(mrow[mi][hf], tm);
                float corr = __expf(mrow[mi][hf] - mnew);
                mrow[mi][hf] = mnew;
                float rs = 0.f;
#pragma unroll
                for (int j = 0; j < 8; j++) {
                    float p0 = __expf(s[mi][j][hf * 2] - mnew);
                    float p1 = __expf(s[mi][j][hf * 2 + 1] - mnew);
                    s[mi][j][hf * 2] = p0; s[mi][j][hf * 2 + 1] = p1;
                    rs += p0 + p1;
                }
                rs += __shfl_xor_sync(0xffffffffu, rs, 1);
                rs += __shfl_xor_sync(0xffffffffu, rs, 2);
                lrow[mi][hf] = lrow[mi][hf] * corr + rs;
#pragma unroll
                for (int j = 0; j < 8; j++) {
                    o[mi][j][hf * 2] *= corr; o[mi][j][hf * 2 + 1] *= corr;
                }
            }

        // ---- O += P V (3-pass, in-register P split) ----
#pragma unroll
        for (int tt = 0; tt < 4; tt++) {
            uint32_t aph[2][4], apl[2][4];
#pragma unroll
            for (int mi = 0; mi < 2; mi++) {
                psplit2(s[mi][2 * tt][0], s[mi][2 * tt][1], aph[mi][0], apl[mi][0]);
                psplit2(s[mi][2 * tt][2], s[mi][2 * tt][3], aph[mi][1], apl[mi][1]);
                psplit2(s[mi][2 * tt + 1][0], s[mi][2 * tt + 1][1], aph[mi][2], apl[mi][2]);
                psplit2(s[mi][2 * tt + 1][2], s[mi][2 * tt + 1][3], aph[mi][3], apl[mi][3]);
            }
            uint32_t bvh[16], bvl[16];
#pragma unroll
            for (int j2 = 0; j2 < 4; j2++) {
                int vrow = tt * 16 + ((lane >> 3) & 1) * 8 + (lane & 7);
                int c16 = j2 * 2 + (lane >> 4);
                uint32_t vd = (uint32_t)(vrow * 128 + ((c16 ^ (vrow & 7)) << 4));
                ldm4t(&bvh[j2 * 4], kb + 16384 + vd);
                ldm4t(&bvl[j2 * 4], kb + 24576 + vd);
            }
#pragma unroll
            for (int mi = 0; mi < 2; mi++)
#pragma unroll
                for (int j = 0; j < 8; j++) {
                    mma16816(o[mi][j], aph[mi], bvh[j * 2], bvh[j * 2 + 1]);
                    mma16816(o[mi][j], aph[mi], bvl[j * 2], bvl[j * 2 + 1]);
                    mma16816(o[mi][j], apl[mi], bvh[j * 2], bvh[j * 2 + 1]);
                }
        }
        __syncthreads();
        if (t + 2 < 16) issueKV(t + 2);
    }

    // ---- epilogue ----
    size_t obase = ((size_t)(b * 1024) + mtile * 128) * 512 + h * 64;
    int r = lane >> 2, c2 = (lane & 3) * 2;
#pragma unroll
    for (int mi = 0; mi < 2; mi++)
#pragma unroll
        for (int hf = 0; hf < 2; hf++) {
            float inv = 1.f / lrow[mi][hf];
            int grow = rbase + mi * 16 + hf * 8 + r;
#pragma unroll
            for (int j = 0; j < 8; j++) {
                float2 v;
                v.x = o[mi][j][hf * 2] * inv;
                v.y = o[mi][j][hf * 2 + 1] * inv;
                *(float2*)&outhi[obase + (size_t)grow * 512 + j * 8 + c2] = v;
            }
        }
}

// ================= prep kernels =================
__device__ __forceinline__ void split4(float4 v, bf16* h, bf16* l, size_t base)
{
    float a[4] = { v.x, v.y, v.z, v.w };
    bf16 hh[4], ll[4];
#pragma unroll
    for (int i = 0; i < 4; i++) {
        hh[i] = __float2bfloat16(a[i]);
        ll[i] = __float2bfloat16(a[i] - __bfloat162float(hh[i]));
    }
    *(uint2*)(h + base) = *(uint2*)hh;
    *(uint2*)(l + base) = *(uint2*)ll;
}

__global__ void split_generic(const float4* __restrict__ src, bf16* __restrict__ h,
                              bf16* __restrict__ l, int n4)
{
    int gid = blockIdx.x * 256 + threadIdx.x;
    if (gid >= n4) return;
    split4(src[gid], h, l, (size_t)gid * 4);
}

__global__ void pool_split(const float* __restrict__ x)
{
    int gid = blockIdx.x * 256 + threadIdx.x;
    int c4 = gid & 127;
    int hw = (gid >> 7) & 1023;
    int b = gid >> 17;
    int wh = hw >> 5, ww = hw & 31;
    int n0 = (wh * 2) * 64 + ww * 2;
    const float4* xb = (const float4*)(x + (size_t)b * Ntok * Cch);
    float4 a = xb[(size_t)n0 * 128 + c4];
    float4 bv = xb[(size_t)(n0 + 1) * 128 + c4];
    float4 c = xb[(size_t)(n0 + 64) * 128 + c4];
    float4 d = xb[(size_t)(n0 + 65) * 128 + c4];
    float4 o;
    o.x = (a.x + bv.x + c.x + d.x) * 0.25f;
    o.y = (a.y + bv.y + c.y + d.y) * 0.25f;
    o.z = (a.z + bv.z + c.z + d.z) * 0.25f;
    o.w = (a.w + bv.w + c.w + d.w) * 0.25f;
    split4(o, g_xhih, g_xhil, (size_t)gid * 4);
}

__global__ void gather_win_split(const float* __restrict__ x)
{
    int gid = blockIdx.x * 256 + threadIdx.x;
    int k4 = gid & 127;
    int m = gid >> 7;
    int t = m & 3, w = (m >> 2) & 1023, b = m >> 12;
    int kp = k4 * 4;
    int p = kp >> 7, q = kp & 127;
    int wh = w >> 5, ww = w & 31;
    int i = p >> 1, j = p & 1;
    int n = (wh * 2 + i) * 64 + ww * 2 + j;
    float4 v = *(const float4*)(x + ((size_t)b * Ntok + n) * Cch + t * 128 + q);
    split4(v, g_winh, g_winl, (size_t)gid * 4);
}

__global__ void permw_split(const float* __restrict__ W)
{
    int gid = blockIdx.x * 256 + threadIdx.x;
    if (gid >= 1536 * 512) return;
    int kp = gid & 511, j = gid >> 9;
    int p = kp >> 7, q = kp & 127;
    float v = W[j * 512 + q * 4 + p];
    bf16 h = __float2bfloat16(v);
    g_Wloh[gid] = h;
    g_Wlol[gid] = __float2bfloat16(v - __bfloat162float(h));
}

__device__ __forceinline__ void up_weights(int y, int& ia, int& ib, float& wa, float& wb)
{
    int m = y >> 1;
    if ((y & 1) == 0) { ia = m - 1 < 0 ? 0 : m - 1; ib = m; wa = 0.25f; wb = 0.75f; }
    else { ia = m; ib = m + 1 > 31 ? 31 : m + 1; wa = 0.75f; wb = 0.25f; }
}

__global__ void upsample_kernel()
{
    int gid = blockIdx.x * 256 + threadIdx.x;
    int c4 = gid & 127;
    int n = (gid >> 7) & 4095;
    int b = gid >> 19;
    int y = n >> 6, x = n & 63;
    int ya, yb2; float wya, wyb;
    int xa, xb2; float wxa, wxb;
    up_weights(y, ya, yb2, wya, wyb);
    up_weights(x, xa, xb2, wxa, wxb);
    const float4* src = (const float4*)(g_out_hi + (size_t)b * NHI * Cch);
    float4 vaa = src[(size_t)(ya * 32 + xa) * 128 + c4];
    float4 vab = src[(size_t)(ya * 32 + xb2) * 128 + c4];
    float4 vba = src[(size_t)(yb2 * 32 + xa) * 128 + c4];
    float4 vbb = src[(size_t)(yb2 * 32 + xb2) * 128 + c4];
    float waa = wya * wxa, wab = wya * wxb, wba = wyb * wxa, wbb = wyb * wxb;
    float4 o;
    o.x = waa * vaa.x + wab * vab.x + wba * vba.x + wbb * vbb.x;
    o.y = waa * vaa.y + wab * vab.y + wba * vba.y + wbb * vbb.y;
    o.z = waa * vaa.z + wab * vab.z + wba * vba.z + wbb * vbb.z;
    o.w = waa * vaa.w + wab * vab.w + wba * vba.w + wbb * vbb.w;
    ((float4*)g_sum)[gid] = o;
}

// lo-branch 4x4 windowed attention: reads g_sum (upsample) + g_qkv_lo,
// writes final split-bf16 sum to g_sumh/g_suml.
__global__ void lo_attn_kernel()
{
    __shared__ __align__(16) float sm[2][4 * 1536];
    int wp = threadIdx.x >> 5;
    int lane = threadIdx.x & 31;
    int widx = blockIdx.x * 2 + wp;
    int b = widx >> 10, w = widx & 1023;

    const float4* src4 = (const float4*)(g_qkv_lo + (size_t)widx * 4 * 1536);
    float4* sm4 = (float4*)sm[wp];
    for (int f = lane; f < 1536; f += 32) sm4[f] = src4[f];
    __syncwarp();

    int h = lane >> 2, ti = lane & 3;
    const float* base = sm[wp];
    const float4* q4 = (const float4*)(base + ti * 1536 + h * 64);
    float s[4];
#pragma unroll
    for (int tj = 0; tj < 4; tj++) {
        const float4* k4 = (const float4*)(base + tj * 1536 + 512 + h * 64);
        float acc = 0.f;
#pragma unroll
        for (int d = 0; d < 16; d++) {
            float4 a = q4[d], kk = k4[d];
            acc += a.x * kk.x + a.y * kk.y + a.z * kk.z + a.w * kk.w;
        }
        s[tj] = acc * 0.125f;
    }
    float mx = fmaxf(fmaxf(s[0], s[1]), fmaxf(s[2], s[3]));
    float p[4], sum = 0.f;
#pragma unroll
    for (int tj = 0; tj < 4; tj++) { p[tj] = __expf(s[tj] - mx); sum += p[tj]; }
    float inv = 1.f / sum;
#pragma unroll
    for (int tj = 0; tj < 4; tj++) p[tj] *= inv;

    int wh = w >> 5, ww = w & 31;
    int nout = (wh * 2 + (ti >> 1)) * 64 + ww * 2 + (ti & 1);
    size_t obase = ((size_t)b * Ntok + nout) * Cch + h * 64;
    const float4* up4 = (const float4*)(g_sum + obase);
    const float4* v0 = (const float4*)(base + 0 * 1536 + 1024 + h * 64);
    const float4* v1 = (const float4*)(base + 1 * 1536 + 1024 + h * 64);
    const float4* v2 = (const float4*)(base + 2 * 1536 + 1024 + h * 64);
    const float4* v3 = (const float4*)(base + 3 * 1536 + 1024 + h * 64);
#pragma unroll
    for (int d = 0; d < 16; d++) {
        float4 o = up4[d];
        float4 a = v0[d], bb = v1[d], c = v2[d], e = v3[d];
        o.x += p[0] * a.x + p[1] * bb.x + p[2] * c.x + p[3] * e.x;
        o.y += p[0] * a.y + p[1] * bb.y + p[2] * c.y + p[3] * e.y;
        o.z += p[0] * a.z + p[1] * bb.z + p[2] * c.z + p[3] * e.z;
        o.w += p[0] * a.w + p[1] * bb.w + p[2] * c.w + p[3] * e.w;
        split4(o, g_sumh, g_suml, obase + d * 4);
    }
}

// ================= Launch =================
extern "C" void kernel_launch(void* const* d_in, const int* in_sizes, int n_in,
                              void* d_out, int out_size)
{
    const float* x = (const float*)d_in[0];
    const float* Wqkv = (const float*)d_in[1];
    const float* Wproj = (const float*)d_in[2];
    const float* bproj = (const float*)d_in[3];
    float* out = (float*)d_out;

    float *outhi, *qkvlo;
    bf16 *xhih, *xhil, *Wqh, *Wql, *qh, *ql;
    bf16 *winh, *winl, *Wloh, *Wlol, *sumh, *suml, *Wph, *Wpl;
    cudaGetSymbolAddress((void**)&outhi, g_out_hi);
    cudaGetSymbolAddress((void**)&qkvlo, g_qkv_lo);
    cudaGetSymbolAddress((void**)&xhih, g_xhih);
    cudaGetSymbolAddress((void**)&xhil, g_xhil);
    cudaGetSymbolAddress((void**)&Wqh, g_Wqh);
    cudaGetSymbolAddress((void**)&Wql, g_Wql);
    cudaGetSymbolAddress((void**)&qh, g_qh);
    cudaGetSymbolAddress((void**)&ql, g_ql);
    cudaGetSymbolAddress((void**)&winh, g_winh);
    cudaGetSymbolAddress((void**)&winl, g_winl);
    cudaGetSymbolAddress((void**)&Wloh, g_Wloh);
    cudaGetSymbolAddress((void**)&Wlol, g_Wlol);
    cudaGetSymbolAddress((void**)&sumh, g_sumh);
    cudaGetSymbolAddress((void**)&suml, g_suml);
    cudaGetSymbolAddress((void**)&Wph, g_Wph);
    cudaGetSymbolAddress((void**)&Wpl, g_Wpl);

    const int SMEM128 = 2 * (32768 + 2 * 128 * 128);  // 131072
    const int SMEMFA  = 32768 + 2 * 32768;            //  98304
    cudaFuncSetAttribute(mma_gemm<128, 0>, cudaFuncAttributeMaxDynamicSharedMemorySize, SMEM128);
    cudaFuncSetAttribute(mma_gemm<128, 1>, cudaFuncAttributeMaxDynamicSharedMemorySize, SMEM128);
    cudaFuncSetAttribute(mma_gemm<128, 2>, cudaFuncAttributeMaxDynamicSharedMemorySize, SMEM128);
    cudaFuncSetAttribute(flash_hi, cudaFuncAttributeMaxDynamicSharedMemorySize, SMEMFA);

    // input prep
    pool_split<<<4096, 256>>>(x);
    split_generic<<<768, 256>>>((const float4*)Wqkv, Wqh, Wql, 196608);
    gather_win_split<<<16384, 256>>>(x);
    permw_split<<<3072, 256>>>(Wqkv);
    split_generic<<<256, 256>>>((const float4*)Wproj, Wph, Wpl, 65536);

    // qkv_hi = x_hi @ W_qkv^T : [8192 x 1536], K=512 -> split bf16 qh/ql
    mma_gemm<128, 2><<<dim3(12, 64, 1), 256, SMEM128>>>(
        xhih, xhil, 512, 0, 0, Wqh, Wql, 512, 0, 0,
        nullptr, qh, ql, 1536, 0, 0, nullptr, 512, 1.f, 1);

    // fused hi attention -> out_hi fp32
    flash_hi<<<dim3(8, 64), 128, SMEMFA>>>(qh, ql, outhi);

    upsample_kernel<<<16384, 256>>>();

    // qkv_lo = windows @ W_lo^T : [32768 x 1536], K=512 -> fp32
    mma_gemm<128, 0><<<dim3(12, 256, 1), 256, SMEM128>>>(
        winh, winl, 512, 0, 0, Wloh, Wlol, 512, 0, 0,
        qkvlo, nullptr, nullptr, 1536, 0, 0, nullptr, 512, 1.f, 1);

    // lo attention + add upsample -> split bf16 sumh/suml
    lo_attn_kernel<<<4096, 64>>>();

    // out = sum @ W_proj^T + b : [32768 x 512], K=512
    mma_gemm<128, 1><<<dim3(4, 256, 1), 256, SMEM128>>>(
        sumh, suml, 512, 0, 0, Wph, Wpl, 512, 0, 0,
        out, nullptr, nullptr, 512, 0, 0, bproj, 512, 1.f, 1);
}